// round 10
// baseline (speedup 1.0000x reference)
#include <cuda_runtime.h>
#include <cstdint>

// Problem constants (fixed instance)
constexpr int S   = 16;
constexpr int EXT = 64;
constexpr int SE  = S * EXT;          // 1024
constexpr int NN  = 8192;             // nodes
constexpr int EE  = 16384;            // edges
constexpr int PP  = 2048;             // paths

// Dense coefficient tensor, duplicated into float2 {c,c} so LDS.128 yields two
// ready f32x2 operands. Layout: idx = (i*16 + j)*16 + k   (k contiguous)
__device__ __align__(16) float2 g_C2[S * S * S];

// ---------------- f32x2 packed helpers (sm_103a) ----------------
__device__ __forceinline__ unsigned long long f32x2_pack(float lo, float hi) {
    unsigned long long d;
    asm("mov.b64 %0, {%1, %2};" : "=l"(d) : "f"(lo), "f"(hi));
    return d;
}
__device__ __forceinline__ void f32x2_unpack(unsigned long long v, float& lo, float& hi) {
    asm("mov.b64 {%0, %1}, %2;" : "=f"(lo), "=f"(hi) : "l"(v));
}
__device__ __forceinline__ unsigned long long f32x2_mul(unsigned long long a, unsigned long long b) {
    unsigned long long d;
    asm("mul.rn.f32x2 %0, %1, %2;" : "=l"(d) : "l"(a), "l"(b));
    return d;
}
__device__ __forceinline__ unsigned long long f32x2_fma(unsigned long long a, unsigned long long b,
                                                        unsigned long long c) {
    unsigned long long d;
    asm("fma.rn.f32x2 %0, %1, %2, %3;" : "=l"(d) : "l"(a), "l"(b), "l"(c));
    return d;
}

// ---------------- setup kernels ----------------
__global__ void zero_c_kernel() {
    int t = blockIdx.x * blockDim.x + threadIdx.x;
    if (t < S * S * S) g_C2[t] = make_float2(0.0f, 0.0f);
}

__global__ void build_c_kernel(const int* __restrict__ path_indices,
                               const float* __restrict__ path_coeffs) {
    int p = blockIdx.x * blockDim.x + threadIdx.x;
    if (p >= PP) return;
    int i = path_indices[3 * p + 0];   // x segment
    int j = path_indices[3 * p + 1];   // y segment
    int k = path_indices[3 * p + 2];   // out segment
    float cf = path_coeffs[p];
    int idx = (i * S + j) * S + k;
    atomicAdd(&g_C2[idx].x, cf);
    atomicAdd(&g_C2[idx].y, cf);
}

__global__ void zero_out_kernel(float4* __restrict__ out, int n4) {
    int t = blockIdx.x * blockDim.x + threadIdx.x;
    if (t < n4) out[t] = make_float4(0.0f, 0.0f, 0.0f, 0.0f);
}

// ---------------- main contraction ----------------
// Thread decomposition: each thread owns 2 edges x 4 channels x 8 k-values.
//   channels: pair A = (c, c+32), pair B = (c+16, c+48), c = lane & 15
//   k-half:   kh = warp & 1  (warp-uniform -> LDS broadcast stays N=1)
//   edges:    slot s = lane >> 4; thread edges = base + 2*s + {0,1}
// Block 128 threads = 4 warps: warps {0,1} cover edges base..base+3 with
// kh=0/1, warps {2,3} cover edges base+4..base+7. 8 edges/block, grid 2048.
// Per (i,j): 4 LDS.128 feed 32 FFMA2 (2 edges x 2 pairs x 8 k) -> chip LDS
// traffic HALVED vs R4/R8 at equal fma work.
constexpr int EDGES_PER_BLOCK = 8;
constexpr int JC = 8;                  // j-chunk size (two chunks)

__global__ __launch_bounds__(128, 3) void seg_poly_kernel(
    const float* __restrict__ x,
    const float* __restrict__ y,
    const int*   __restrict__ idx_in,
    const int*   __restrict__ idx_out,
    float*       __restrict__ out)
{
    __shared__ __align__(16) float2 Cs[S * S * S];   // 32 KB

    // cooperative load of C (vectorized)
    {
        const float4* src = reinterpret_cast<const float4*>(g_C2);
        float4* dst = reinterpret_cast<float4*>(Cs);
        for (int t = threadIdx.x; t < (S * S * S) / 2; t += 128)
            dst[t] = src[t];
    }
    __syncthreads();

    const int w    = threadIdx.x >> 5;       // warp 0..3
    const int lane = threadIdx.x & 31;
    const int kh   = w & 1;                  // k-half (warp-uniform)
    const int s    = lane >> 4;              // edge-pair slot 0/1
    const int c    = lane & 15;              // base channel

    const int eb = blockIdx.x * EDGES_PER_BLOCK + (w >> 1) * 4 + s * 2;  // edges eb, eb+1

    const int xrow0 = idx_in[eb];
    const int xrow1 = idx_in[eb + 1];
    const int orow0 = idx_out[eb];
    const int orow1 = idx_out[eb + 1];

    const float* xp0 = x + (size_t)xrow0 * SE + c;
    const float* xp1 = x + (size_t)xrow1 * SE + c;
    const float* yp0 = y + (size_t)eb       * SE + c;
    const float* yp1 = y + (size_t)(eb + 1) * SE + c;

    // acc[edge][pair][k8] : 2*2*8 f32x2 = 64 regs
    unsigned long long accA0[8], accA1[8], accB0[8], accB1[8];
    #pragma unroll
    for (int k = 0; k < 8; ++k) { accA0[k] = 0ULL; accA1[k] = 0ULL; accB0[k] = 0ULL; accB1[k] = 0ULL; }

    #pragma unroll 1
    for (int jc = 0; jc < S; jc += JC) {
        // y chunk: 2 edges x 2 pairs x JC f32x2 = 64 regs
        unsigned long long yA0[JC], yA1[JC], yB0[JC], yB1[JC];
        {
            const float* q0 = yp0 + jc * EXT;
            const float* q1 = yp1 + jc * EXT;
            #pragma unroll
            for (int j = 0; j < JC; ++j) {
                yA0[j] = f32x2_pack(q0[j * EXT     ], q0[j * EXT + 32]);
                yB0[j] = f32x2_pack(q0[j * EXT + 16], q0[j * EXT + 48]);
                yA1[j] = f32x2_pack(q1[j * EXT     ], q1[j * EXT + 32]);
                yB1[j] = f32x2_pack(q1[j * EXT + 16], q1[j * EXT + 48]);
            }
        }

        const float2* crow = Cs + (jc * S) + kh * 8;   // advance by S*S per i
        const float* xq0 = xp0;
        const float* xq1 = xp1;
        #pragma unroll 1
        for (int i = 0; i < S; ++i) {
            const unsigned long long aA0 = f32x2_pack(xq0[0],  xq0[32]);
            const unsigned long long aB0 = f32x2_pack(xq0[16], xq0[48]);
            const unsigned long long aA1 = f32x2_pack(xq1[0],  xq1[32]);
            const unsigned long long aB1 = f32x2_pack(xq1[16], xq1[48]);
            xq0 += EXT; xq1 += EXT;

            #pragma unroll
            for (int j = 0; j < JC; ++j) {
                const unsigned long long pA0 = f32x2_mul(aA0, yA0[j]);
                const unsigned long long pB0 = f32x2_mul(aB0, yB0[j]);
                const unsigned long long pA1 = f32x2_mul(aA1, yA1[j]);
                const unsigned long long pB1 = f32x2_mul(aB1, yB1[j]);
                const ulonglong2* cp = reinterpret_cast<const ulonglong2*>(crow + j * S);
                #pragma unroll
                for (int kk = 0; kk < 4; ++kk) {
                    ulonglong2 cc = cp[kk];           // LDS.128: {C[2kk]x2, C[2kk+1]x2} of this k-half
                    accA0[2 * kk]     = f32x2_fma(cc.x, pA0, accA0[2 * kk]);
                    accB0[2 * kk]     = f32x2_fma(cc.x, pB0, accB0[2 * kk]);
                    accA1[2 * kk]     = f32x2_fma(cc.x, pA1, accA1[2 * kk]);
                    accB1[2 * kk]     = f32x2_fma(cc.x, pB1, accB1[2 * kk]);
                    accA0[2 * kk + 1] = f32x2_fma(cc.y, pA0, accA0[2 * kk + 1]);
                    accB0[2 * kk + 1] = f32x2_fma(cc.y, pB0, accB0[2 * kk + 1]);
                    accA1[2 * kk + 1] = f32x2_fma(cc.y, pA1, accA1[2 * kk + 1]);
                    accB1[2 * kk + 1] = f32x2_fma(cc.y, pB1, accB1[2 * kk + 1]);
                }
            }
            crow += S * S;
        }
    }

    // scatter-add: 2 edges x 8 k x 4 channels = 64 atomics/thread
    {
        float* op0 = out + (size_t)orow0 * SE + kh * 8 * EXT + c;
        float* op1 = out + (size_t)orow1 * SE + kh * 8 * EXT + c;
        #pragma unroll
        for (int k = 0; k < 8; ++k) {
            float a0, a1, b0, b1;
            f32x2_unpack(accA0[k], a0, a1);
            f32x2_unpack(accB0[k], b0, b1);
            atomicAdd(op0 + k * EXT,      a0);
            atomicAdd(op0 + k * EXT + 16, b0);
            atomicAdd(op0 + k * EXT + 32, a1);
            atomicAdd(op0 + k * EXT + 48, b1);
            f32x2_unpack(accA1[k], a0, a1);
            f32x2_unpack(accB1[k], b0, b1);
            atomicAdd(op1 + k * EXT,      a0);
            atomicAdd(op1 + k * EXT + 16, b0);
            atomicAdd(op1 + k * EXT + 32, a1);
            atomicAdd(op1 + k * EXT + 48, b1);
        }
    }
}

// ---------------- launch ----------------
extern "C" void kernel_launch(void* const* d_in, const int* in_sizes, int n_in,
                              void* d_out, int out_size)
{
    const float* x        = (const float*)d_in[0];
    const float* y        = (const float*)d_in[1];
    const int*   idx_in   = (const int*)d_in[2];
    const int*   idx_out  = (const int*)d_in[3];
    const int*   path_idx = (const int*)d_in[4];
    const float* path_cf  = (const float*)d_in[5];
    float* out = (float*)d_out;

    zero_c_kernel<<<(S * S * S + 255) / 256, 256>>>();
    build_c_kernel<<<(PP + 255) / 256, 256>>>(path_idx, path_cf);

    int n4 = out_size / 4;  // 8M floats -> 2M float4
    zero_out_kernel<<<(n4 + 511) / 512, 512>>>((float4*)d_out, n4);

    seg_poly_kernel<<<EE / EDGES_PER_BLOCK, 128>>>(x, y, idx_in, idx_out, out);
}